// round 15
// baseline (speedup 1.0000x reference)
#include <cuda_runtime.h>
#include <cuda_fp16.h>
#include <cstdint>

#define BB 2
#define SS 2048
#define EE 1024
#define HH 16
#define DD 64

// Q pre-scale: (1/sqrt(64)) * log2(e)  -> softmax computed in exp2 domain
#define QSCALE 0.18033688011112042f

// Scratch (device globals), fp16 unless noted.
__device__ __half g_Xh[3*BB*SS*EE];      // converted q|k|v inputs [3][4096][1024]
__device__ __half g_Qh[BB*HH*SS*DD];     // [bh][s][d], pre-scaled by log2e/8
__device__ __half g_Kh[BB*HH*SS*DD];     // [bh][s][d]
__device__ __half g_Vh[BB*HH*SS*DD];     // [bh][s][d]
__device__ __half g_ctxh[BB*SS*EE];      // [b*s][e]
__device__ __half g_Wqt[3*EE*EE];        // Wqkv^T [3072][1024]
__device__ __half g_Wot[EE*EE];          // Wout^T [1024][1024]
__device__ uint32_t g_mb[SS*(SS/32)];    // mask bitfield [2048][64]

// ---------------------------------------------------------------------------
__device__ __forceinline__ uint32_t smem_u32(const void* p){
    uint32_t a;
    asm("{ .reg .u64 t; cvta.to.shared.u64 t, %1; cvt.u32.u64 %0, t; }" : "=r"(a) : "l"(p));
    return a;
}
__device__ __forceinline__ void cp16(uint32_t dst, const void* src){
    asm volatile("cp.async.cg.shared.global [%0], [%1], 16;" :: "r"(dst), "l"(src));
}
__device__ __forceinline__ void cp8(uint32_t dst, const void* src){
    asm volatile("cp.async.ca.shared.global [%0], [%1], 8;" :: "r"(dst), "l"(src));
}
#define CP_COMMIT() asm volatile("cp.async.commit_group;")
#define CP_WAIT1()  asm volatile("cp.async.wait_group 1;")
#define CP_WAIT0()  asm volatile("cp.async.wait_group 0;")

__device__ __forceinline__ void ldsm4(uint32_t addr, uint32_t r[4]){
    asm volatile("ldmatrix.sync.aligned.m8n8.x4.shared.b16 {%0,%1,%2,%3}, [%4];"
        : "=r"(r[0]), "=r"(r[1]), "=r"(r[2]), "=r"(r[3]) : "r"(addr));
}
__device__ __forceinline__ void ldsm4t(uint32_t addr, uint32_t r[4]){
    asm volatile("ldmatrix.sync.aligned.m8n8.x4.trans.shared.b16 {%0,%1,%2,%3}, [%4];"
        : "=r"(r[0]), "=r"(r[1]), "=r"(r[2]), "=r"(r[3]) : "r"(addr));
}
__device__ __forceinline__ void mma16(float c[4], const uint32_t a[4], uint32_t b0, uint32_t b1){
    asm volatile(
        "mma.sync.aligned.m16n8k16.row.col.f32.f16.f16.f32 "
        "{%0,%1,%2,%3}, {%4,%5,%6,%7}, {%8,%9}, {%0,%1,%2,%3};"
        : "+f"(c[0]), "+f"(c[1]), "+f"(c[2]), "+f"(c[3])
        : "r"(a[0]), "r"(a[1]), "r"(a[2]), "r"(a[3]), "r"(b0), "r"(b1));
}
__device__ __forceinline__ uint32_t packh2(float lo, float hi){
    __half2 h = __floats2half2_rn(lo, hi);
    return *(uint32_t*)&h;
}
__device__ __forceinline__ uint32_t h2exp2(uint32_t d){
    uint32_t r; asm("ex2.approx.f16x2 %0, %1;" : "=r"(r) : "r"(d)); return r;
}

// ---------------------------------------------------------------------------
// Fused prep kernel: block ranges dispatch the 4 former prep kernels.
// ---------------------------------------------------------------------------
__global__ void prep_kernel(const float* __restrict__ q, const float* __restrict__ k,
                            const float* __restrict__ v, const float* __restrict__ Wqkv,
                            const float* __restrict__ Wout, const int* __restrict__ mask)
{
    const int blk = blockIdx.x;
    const int tid = threadIdx.x;

    if (blk < 6144) {
        int sec = blk / 2048;
        const float* src = (sec == 0) ? q : (sec == 1) ? k : v;
        size_t i = ((size_t)(blk % 2048) * 256 + tid) * 8;
        float4 f0 = *(const float4*)(src + i);
        float4 f1 = *(const float4*)(src + i + 4);
        uint4 u;
        u.x = packh2(f0.x, f0.y); u.y = packh2(f0.z, f0.w);
        u.z = packh2(f1.x, f1.y); u.w = packh2(f1.z, f1.w);
        *(uint4*)(g_Xh + (size_t)sec * (BB*SS*EE) + i) = u;
    } else if (blk < 10240) {
        __shared__ float t[32][33];
        int isout = (blk >= 9216);
        int bb = blk - (isout ? 9216 : 6144);
        int nblk = isout ? 32 : 96;
        int cols = isout ? EE : 3 * EE;
        const float* W = isout ? Wout : Wqkv;
        __half* Wt = isout ? g_Wot : g_Wqt;
        int n0 = (bb % nblk) << 5, k0 = (bb / nblk) << 5;
        int tx = tid & 31, ty = tid >> 5;
        #pragma unroll
        for (int j = 0; j < 32; j += 8)
            t[ty + j][tx] = W[(size_t)(k0 + ty + j) * cols + n0 + tx];
        __syncthreads();
        #pragma unroll
        for (int j = 0; j < 32; j += 8)
            Wt[(size_t)(n0 + ty + j) * EE + k0 + tx] = __float2half(t[tx][ty + j]);
    } else {
        int gw = ((blk - 10240) * 256 + tid) >> 5;
        int lane = tid & 31;
        int s = gw >> 3;
        int w0 = (gw & 7) << 3;
        const int* base = mask + (size_t)s * SS + (w0 << 5) + lane;
        uint32_t out[8];
        #pragma unroll
        for (int j = 0; j < 8; ++j)
            out[j] = __ballot_sync(0xffffffffu, base[j * 32] != 0);
        if (lane == 0) {
            *(uint4*)(g_mb + (size_t)s * 64 + w0)     = make_uint4(out[0], out[1], out[2], out[3]);
            *(uint4*)(g_mb + (size_t)s * 64 + w0 + 4) = make_uint4(out[4], out[5], out[6], out[7]);
        }
    }
}

// ---------------------------------------------------------------------------
// fp16 mma GEMM: 3-stage cp.async ring, depth-1 prefetch, ONE barrier/iter.
// CTA 128x128, 8 warps (4m x 2n), k-tile 64.
// ---------------------------------------------------------------------------
#define GS 144
#define G_A_BYTES (128*GS)           // 18432
#define G_STAGE (2*G_A_BYTES)        // 36864
#define G_SMEM (3*G_STAGE)           // 110592

__device__ __forceinline__ void gemm_fp16(
    const __half* __restrict__ A,
    const __half* __restrict__ Wt,
    const float* __restrict__ bias,
    float* __restrict__ Cout, int mode, int n0)
{
    extern __shared__ char smc[];
    const uint32_t smb = smem_u32(smc);
    const int tid = threadIdx.x, lane = tid & 31, wid = tid >> 5;
    const int g = lane >> 2, qp = lane & 3;
    const int m0 = blockIdx.y << 7;
    const int wm0 = (wid & 3) << 5, wn0 = (wid >> 2) << 6;

    uint32_t aAddr[2], bAddr[4];
    #pragma unroll
    for (int mf = 0; mf < 2; ++mf)
        aAddr[mf] = smb + (wm0 + mf * 16 + (lane & 15)) * GS + ((lane >> 4) << 4);
    #pragma unroll
    for (int p = 0; p < 4; ++p)
        bAddr[p] = smb + G_A_BYTES
                 + (wn0 + p * 16 + ((lane >> 4) << 3) + (lane & 7)) * GS
                 + (((lane >> 3) & 1) << 4);

    float acc[2][8][4] = {};

    #define G_LOAD(stage, kt) do { \
        uint32_t ab = smb + (stage) * G_STAGE; \
        uint32_t bb = ab + G_A_BYTES; \
        _Pragma("unroll") \
        for (int it = 0; it < 4; ++it) { \
            int idx = tid + (it << 8); \
            int r = idx >> 3, c = idx & 7; \
            cp16(ab + r * GS + c * 16, A  + (size_t)(m0 + r) * EE + (kt) + c * 8); \
            cp16(bb + r * GS + c * 16, Wt + (size_t)(n0 + r) * EE + (kt) + c * 8); \
        } \
    } while (0)

    G_LOAD(0, 0);
    CP_COMMIT();

    int cur = 0, nxt = 1;
    for (int t = 0; t < 16; ++t) {
        if (t < 15) { G_LOAD(nxt, (t + 1) << 6); CP_COMMIT(); CP_WAIT1(); }
        else        { CP_WAIT0(); }
        __syncthreads();
        const uint32_t sOff = cur * G_STAGE;

        #pragma unroll
        for (int ks = 0; ks < 4; ++ks) {
            uint32_t a[2][4];
            ldsm4(aAddr[0] + sOff + ks * 32, a[0]);
            ldsm4(aAddr[1] + sOff + ks * 32, a[1]);
            #pragma unroll
            for (int p = 0; p < 4; ++p) {
                uint32_t bq[4];
                ldsm4(bAddr[p] + sOff + ks * 32, bq);
                mma16(acc[0][2*p],   a[0], bq[0], bq[1]);
                mma16(acc[1][2*p],   a[1], bq[0], bq[1]);
                mma16(acc[0][2*p+1], a[0], bq[2], bq[3]);
                mma16(acc[1][2*p+1], a[1], bq[2], bq[3]);
            }
        }
        cur = nxt; nxt = (nxt == 2) ? 0 : nxt + 1;
    }

    // epilogue
    #pragma unroll
    for (int mf = 0; mf < 2; ++mf) {
        #pragma unroll
        for (int nf = 0; nf < 8; ++nf) {
            int n = n0 + wn0 + nf * 8 + 2 * qp;
            float b0v = bias[n], b1v = bias[n + 1];
            #pragma unroll
            for (int rr = 0; rr < 2; ++rr) {
                int m = m0 + wm0 + mf * 16 + g + rr * 8;
                float v0 = acc[mf][nf][rr * 2 + 0] + b0v;
                float v1 = acc[mf][nf][rr * 2 + 1] + b1v;
                if (mode == 3) {
                    *(float2*)(Cout + (size_t)m * EE + n) = make_float2(v0, v1);
                } else {
                    int nn = n & 1023;
                    int h = nn >> 6, d = nn & 63;
                    int b = m >> 11, s = m & (SS - 1);
                    size_t off = ((size_t)((b << 4) + h) * SS + s) * DD + d;
                    if (mode == 0)
                        *(uint32_t*)(g_Qh + off) = packh2(v0 * QSCALE, v1 * QSCALE);
                    else if (mode == 1)
                        *(uint32_t*)(g_Kh + off) = packh2(v0, v1);
                    else
                        *(uint32_t*)(g_Vh + off) = packh2(v0, v1);
                }
            }
        }
    }
    #undef G_LOAD
}

__global__ void __launch_bounds__(256, 2)
qkv_mma_kernel(const float* __restrict__ bqkv)
{
    int n0 = blockIdx.x << 7;
    int sec = n0 >> 10;
    gemm_fp16(g_Xh + (size_t)sec * (BB*SS*EE), g_Wqt, bqkv, nullptr, sec, n0);
}

__global__ void __launch_bounds__(256, 2)
out_mma_kernel(const float* __restrict__ bout, float* __restrict__ out)
{
    gemm_fp16(g_ctxh, g_Wot, bout, out, 3, blockIdx.x << 7);
}

// ---------------------------------------------------------------------------
// Flash attention fp16: 128 queries/CTA, 256 threads, chunk 64.
// 4-stage cp.async ring, depth-1 prefetch, ONE barrier/iter.
// DEFERRED-PV pipelining: iteration t issues QK(t), then PV(t-1) (independent
// tensor work that covers the QK->softmax dependency), then softmax(t).
// Bit-identical to the eager order: ...scale a_{t-1}, add P_{t-1}V, scale a_t,
// add P_tV... is preserved.
// ---------------------------------------------------------------------------
#define AQ_BYTES (128*144)           // 18432
#define A_ST_W   19456
#define A_V_OFF  9216
#define A_BM_OFF 18432
#define ATTN_SMEM (AQ_BYTES + 4*A_ST_W)   // 96256

__global__ void __launch_bounds__(256, 2)
attn_mma_kernel()
{
    extern __shared__ char smc[];
    const uint32_t smb = smem_u32(smc);

    const int tid = threadIdx.x, lane = tid & 31, wid = tid >> 5;
    const int g = lane >> 2, qp = lane & 3;
    const int bh = blockIdx.y, q0 = blockIdx.x << 7;
    const int w16 = wid << 4;

    const __half* Qb = g_Qh + (size_t)bh * SS * DD;
    const __half* Kb = g_Kh + (size_t)bh * SS * DD;
    const __half* Vb = g_Vh + (size_t)bh * SS * DD;

    // Q tile cp.async (grouped with stage 0)
    #pragma unroll
    for (int it = 0; it < 4; ++it) {
        int idx = tid + (it << 8);
        int r = idx >> 3, c = idx & 7;
        cp16(smb + r * 144 + c * 16, Qb + (size_t)(q0 + r) * DD + c * 8);
    }

    #define A_LOAD(stage, kc) do { \
        uint32_t sbase = smb + AQ_BYTES + (stage) * A_ST_W; \
        _Pragma("unroll") \
        for (int it = 0; it < 2; ++it) { \
            int idx = tid + (it << 8); \
            int r = idx >> 3, c = idx & 7; \
            cp16(sbase + r * 144 + c * 16, Kb + (size_t)((kc) + r) * DD + c * 8); \
            cp16(sbase + A_V_OFF + r * 144 + c * 16, Vb + (size_t)((kc) + r) * DD + c * 8); \
        } \
        if (tid < 128) \
            cp8(sbase + A_BM_OFF + tid * 8, g_mb + (size_t)(q0 + tid) * 64 + ((kc) >> 5)); \
    } while (0)

    A_LOAD(0, 0);
    CP_COMMIT();                 // g0 = Q + stage0

    // fragment base addrs
    const uint32_t qBase = smb + (w16 + (lane & 15)) * 144 + ((lane >> 4) << 4);
    uint32_t kBase[4], vBase[4];
    #pragma unroll
    for (int p = 0; p < 4; ++p) {
        kBase[p] = (p * 16 + ((lane >> 4) << 3) + (lane & 7)) * 144 + (((lane >> 3) & 1) << 4);
        vBase[p] = A_V_OFF + (((lane >> 3) & 1) * 8 + (lane & 7)) * 144
                 + ((2 * p + (lane >> 4)) << 4);
    }

    // Q fragments -> registers (stage 0 + Q complete)
    CP_WAIT0();
    __syncthreads();
    uint32_t qa[4][4];
    #pragma unroll
    for (int ks = 0; ks < 4; ++ks) ldsm4(qBase + ks * 32, qa[ks]);

    float o[8][4] = {};
    uint32_t ph[8][2];                                     // P of previous chunk
    __half2 mih = __floats2half2_rn(-60000.f, -60000.f);   // (m_row0, m_row1)
    float li0 = 0.f, li1 = 0.f;                            // per-lane partial sums

    for (int t = 0; t < 32; ++t) {
        if (t < 31) { A_LOAD((t + 1) & 3, (t + 1) << 6); CP_COMMIT(); CP_WAIT1(); }
        else        { CP_WAIT0(); }
        __syncthreads();
        const uint32_t sOff = smb + AQ_BYTES + (t & 3) * A_ST_W;

        // mask bits first: LDS latency hides under the MMAs below
        const uint32_t* bmW = (const uint32_t*)(smc + (sOff - smb) + A_BM_OFF);
        uint2 m0 = *(const uint2*)(bmW + (w16 + g) * 2);
        uint2 m1 = *(const uint2*)(bmW + (w16 + g + 8) * 2);

        // S = Q @ K^T  (log2-domain scores)
        float sacc[8][4] = {};
        #pragma unroll
        for (int ks = 0; ks < 4; ++ks) {
            #pragma unroll
            for (int p = 0; p < 4; ++p) {
                uint32_t bq[4];
                ldsm4(sOff + kBase[p] + ks * 32, bq);
                mma16(sacc[2*p],   qa[ks], bq[0], bq[1]);
                mma16(sacc[2*p+1], qa[ks], bq[2], bq[3]);
            }
        }

        // deferred PV of the PREVIOUS chunk: independent tensor work that
        // executes while the QK results drain (fills the softmax bubble)
        if (t > 0) {
            const uint32_t sPrev = smb + AQ_BYTES + ((t - 1) & 3) * A_ST_W;
            #pragma unroll
            for (int ks = 0; ks < 4; ++ks) {
                uint32_t a2[4] = { ph[2*ks][0], ph[2*ks][1], ph[2*ks+1][0], ph[2*ks+1][1] };
                #pragma unroll
                for (int p = 0; p < 4; ++p) {
                    uint32_t bq[4];
                    ldsm4t(sPrev + vBase[p] + ks * (16 * 144), bq);
                    mma16(o[2*p],   a2, bq[0], bq[1]);
                    mma16(o[2*p+1], a2, bq[2], bq[3]);
                }
            }
        }

        // mask + per-thread row max
        float rm0 = -1e30f, rm1 = -1e30f;
        #pragma unroll
        for (int nf = 0; nf < 8; ++nf) {
            int sh = (nf * 8 + 2 * qp) & 31;
            uint32_t w0 = (nf & 4) ? m0.y : m0.x;
            uint32_t w1 = (nf & 4) ? m1.y : m1.x;
            if (!((w0 >> sh) & 1u))       sacc[nf][0] = -1e30f;
            if (!((w0 >> (sh + 1)) & 1u)) sacc[nf][1] = -1e30f;
            if (!((w1 >> sh) & 1u))       sacc[nf][2] = -1e30f;
            if (!((w1 >> (sh + 1)) & 1u)) sacc[nf][3] = -1e30f;
            rm0 = fmaxf(rm0, fmaxf(sacc[nf][0], sacc[nf][1]));
            rm1 = fmaxf(rm1, fmaxf(sacc[nf][2], sacc[nf][3]));
        }
        // packed half2 max reduction across the 4 qp lanes (2 shuffles)
        uint32_t rmh = packh2(rm0, rm1);
        { __half2 a2 = *(__half2*)&rmh;
          uint32_t s1 = __shfl_xor_sync(0xffffffffu, rmh, 1);
          a2 = __hmax2(a2, *(__half2*)&s1);
          uint32_t ab = *(uint32_t*)&a2;
          uint32_t s2 = __shfl_xor_sync(0xffffffffu, ab, 2);
          a2 = __hmax2(a2, *(__half2*)&s2);
          rmh = *(uint32_t*)&a2; }
        __half2 mnh = __hmax2(mih, *(__half2*)&rmh);
        float mn0 = __low2float(mnh),  mn1 = __high2float(mnh);
        float al0 = exp2f(__low2float(mih) - mn0);
        float al1 = exp2f(__high2float(mih) - mn1);
        mih = mnh;

        // rescale o AFTER PV(t-1) landed (scoreboard orders mma->fmul)
        li0 *= al0;
        li1 *= al1;
        if (!(al0 == 1.f && al1 == 1.f)) {
            #pragma unroll
            for (int nf = 0; nf < 8; ++nf) {
                o[nf][0] *= al0; o[nf][1] *= al0;
                o[nf][2] *= al1; o[nf][3] *= al1;
            }
        }

        // P = 2^(s - m) via fp16x2 MUFU; per-lane partial row sums
        float rs0 = 0.f, rs1 = 0.f;
        #pragma unroll
        for (int nf = 0; nf < 8; ++nf) {
            uint32_t hp0 = h2exp2(packh2(sacc[nf][0] - mn0, sacc[nf][1] - mn0));
            uint32_t hp1 = h2exp2(packh2(sacc[nf][2] - mn1, sacc[nf][3] - mn1));
            ph[nf][0] = hp0;
            ph[nf][1] = hp1;
            float2 f0 = __half22float2(*(__half2*)&hp0);
            float2 f1 = __half22float2(*(__half2*)&hp1);
            rs0 += f0.x + f0.y;
            rs1 += f1.x + f1.y;
        }
        li0 += rs0;
        li1 += rs1;
    }

    // final deferred PV for chunk 31 (stage 31&3 = 3 still valid)
    {
        const uint32_t sLast = smb + AQ_BYTES + 3 * A_ST_W;
        #pragma unroll
        for (int ks = 0; ks < 4; ++ks) {
            uint32_t a2[4] = { ph[2*ks][0], ph[2*ks][1], ph[2*ks+1][0], ph[2*ks+1][1] };
            #pragma unroll
            for (int p = 0; p < 4; ++p) {
                uint32_t bq[4];
                ldsm4t(sLast + vBase[p] + ks * (16 * 144), bq);
                mma16(o[2*p],   a2, bq[0], bq[1]);
                mma16(o[2*p+1], a2, bq[2], bq[3]);
            }
        }
    }

    // deferred l-reduction across the 4 qp lanes (once)
    li0 += __shfl_xor_sync(0xffffffffu, li0, 1);
    li0 += __shfl_xor_sync(0xffffffffu, li0, 2);
    li1 += __shfl_xor_sync(0xffffffffu, li1, 1);
    li1 += __shfl_xor_sync(0xffffffffu, li1, 2);

    // epilogue: ctx[b][q][h*64+d] fp16
    float inv0 = 1.0f / li0, inv1 = 1.0f / li1;
    int b = bh >> 4, h = bh & 15;
    #pragma unroll
    for (int nf = 0; nf < 8; ++nf) {
        int d = nf * 8 + 2 * qp;
        size_t r0 = (size_t)((b << 11) + q0 + w16 + g) * EE + (h << 6) + d;
        size_t r1 = (size_t)((b << 11) + q0 + w16 + g + 8) * EE + (h << 6) + d;
        *(uint32_t*)(g_ctxh + r0) = packh2(o[nf][0] * inv0, o[nf][1] * inv0);
        *(uint32_t*)(g_ctxh + r1) = packh2(o[nf][2] * inv1, o[nf][3] * inv1);
    }
}

// ---------------------------------------------------------------------------
extern "C" void kernel_launch(void* const* d_in, const int* in_sizes, int n_in,
                              void* d_out, int out_size)
{
    const float* q    = (const float*)d_in[0];
    const float* k    = (const float*)d_in[1];
    const float* v    = (const float*)d_in[2];
    const int*   mask = (const int*)  d_in[3];
    const float* Wqkv = (const float*)d_in[4];
    const float* bqkv = (const float*)d_in[5];
    const float* Wout = (const float*)d_in[6];
    const float* bout = (const float*)d_in[7];
    float* out = (float*)d_out;

    cudaFuncSetAttribute(qkv_mma_kernel, cudaFuncAttributeMaxDynamicSharedMemorySize, G_SMEM);
    cudaFuncSetAttribute(out_mma_kernel, cudaFuncAttributeMaxDynamicSharedMemorySize, G_SMEM);
    cudaFuncSetAttribute(attn_mma_kernel, cudaFuncAttributeMaxDynamicSharedMemorySize, ATTN_SMEM);

    // fused prep (one launch)
    prep_kernel<<<12288, 256>>>(q, k, v, Wqkv, Wout, mask);

    // 1) fused QKV projection
    qkv_mma_kernel<<<dim3(24, 32), 256, G_SMEM>>>(bqkv);
    // 2) flash attention (deferred-PV pipelined)
    attn_mma_kernel<<<dim3(SS / 128, BB * HH), 256, ATTN_SMEM>>>();
    // 3) output projection
    out_mma_kernel<<<dim3(8, 32), 256, G_SMEM>>>(bout, out);
}